// round 9
// baseline (speedup 1.0000x reference)
#include <cuda_runtime.h>
#include <cstdint>

#define NROWS 8192
#define NCOLS 2048
#define ORDER 8
#define NB    148
#define TPB   512

typedef unsigned long long ull;

// chunk partial dots: [row][k(8)][chunk(16)] -> 128 floats per row
__device__ float g_Apart[NROWS * 128];

__device__ __forceinline__ ull pack2(float lo, float hi) {
    ull r; asm("mov.b64 %0, {%1, %2};" : "=l"(r) : "f"(lo), "f"(hi)); return r;
}
__device__ __forceinline__ float2 unpack2(ull v) {
    float2 f; asm("mov.b64 {%0, %1}, %2;" : "=f"(f.x), "=f"(f.y) : "l"(v)); return f;
}
__device__ __forceinline__ ull ffma2(ull a, ull b, ull c) {
    ull d; asm("fma.rn.f32x2 %0, %1, %2, %3;" : "=l"(d) : "l"(a), "l"(b), "l"(c)); return d;
}
__device__ __forceinline__ ull fmul2(ull a, ull b) {
    ull d; asm("mul.rn.f32x2 %0, %1, %2;" : "=l"(d) : "l"(a), "l"(b)); return d;
}

// =====================================================================
// k1: chunked partial dots, ZERO barriers.
// warp w owns cols [w*128, w*128+128); 8-row unroll for DRAM MLP.
// =====================================================================
__global__ void __launch_bounds__(TPB, 1) k1_dots(
    const float* __restrict__ x, const float* __restrict__ v)
{
    const int t = threadIdx.x, lane = t & 31, w = t >> 5;
    const int c0 = w * 128 + lane * 4;

    ull V0[ORDER], V1[ORDER];
#pragma unroll
    for (int k = 0; k < ORDER; ++k) {
        const float4 vv = *reinterpret_cast<const float4*>(v + k * NCOLS + c0);
        V0[k] = pack2(vv.x, vv.y);
        V1[k] = pack2(vv.z, vv.w);
    }

    const int bid = blockIdx.x;
    const int nr = (bid < 52) ? 56 : 55;
    const int r0 = (bid < 52) ? bid * 56 : 52 * 56 + (bid - 52) * 55;
    const float* xp = x + c0;

#pragma unroll 1
    for (int tile = 0; tile < 7; ++tile) {
        float4 xr[8];
#pragma unroll
        for (int j = 0; j < 8; ++j) {
            const int jr = tile * 8 + j;
            const int rc = (jr < nr) ? jr : (nr - 1);     // clamped load
            xr[j] = *reinterpret_cast<const float4*>(xp + (size_t)(r0 + rc) * NCOLS);
        }
#pragma unroll
        for (int j = 0; j < 8; ++j) {
            const int jr = tile * 8 + j;
            const ull x01 = pack2(xr[j].x, xr[j].y);
            const ull x23 = pack2(xr[j].z, xr[j].w);
            float p[8];
#pragma unroll
            for (int k = 0; k < 8; ++k) {
                const float2 f = unpack2(ffma2(x23, V1[k], fmul2(x01, V0[k])));
                p[k] = f.x + f.y;
            }
            // folded butterfly: lanes 0..7 end with chunk total for k = lane
#pragma unroll
            for (int k = 0; k < 8; ++k) {
                p[k] += __shfl_xor_sync(0xffffffffu, p[k], 16);
                p[k] += __shfl_xor_sync(0xffffffffu, p[k], 8);
            }
            const bool h4 = (lane & 4) != 0;
            float q[4];
#pragma unroll
            for (int jj = 0; jj < 4; ++jj) {
                float keep = h4 ? p[jj + 4] : p[jj];
                float send = h4 ? p[jj] : p[jj + 4];
                q[jj] = keep + __shfl_xor_sync(0xffffffffu, send, 4);
            }
            const bool h2 = (lane & 2) != 0;
            float r2[2];
#pragma unroll
            for (int jj = 0; jj < 2; ++jj) {
                float keep = h2 ? q[jj + 2] : q[jj];
                float send = h2 ? q[jj] : q[jj + 2];
                r2[jj] = keep + __shfl_xor_sync(0xffffffffu, send, 2);
            }
            const bool h1 = (lane & 1) != 0;
            float keep = h1 ? r2[1] : r2[0];
            float send = h1 ? r2[0] : r2[1];
            const float s = keep + __shfl_xor_sync(0xffffffffu, send, 1);
            // layout: [row][k][chunk]; lane (=k) picks the 16-wide group, w the slot
            if (lane < 8 && jr < nr)
                g_Apart[(size_t)(r0 + jr) * 128 + lane * 16 + w] = s;
        }
    }
}

// =====================================================================
// k2: prologue (Gram -> T' -> W2 = Tneg*V, collapse A partials), ONE
// barrier region, then pure independent streaming correction.
// =====================================================================
__global__ void __launch_bounds__(TPB, 1) k2_stream(
    const float* __restrict__ x, const float* __restrict__ v,
    const float* __restrict__ d, const float* __restrict__ bias,
    float* __restrict__ y)
{
    __shared__ float gpart[16 * 36];
    __shared__ float Tneg[64];
    __shared__ float A2[56 * 8 * 2];   // duplicated (A,A) pairs per (row,i)

    const int t = threadIdx.x, lane = t & 31, w = t >> 5;
    const int c0 = t * 4;

    const int bid = blockIdx.x;
    const int nr = (bid < 52) ? 56 : 55;
    const int r0 = (bid < 52) ? bid * 56 : 52 * 56 + (bid - 52) * 55;

    // ---- V slice (transient; dropped after W2 build) ----
    float4 Vf[ORDER];
#pragma unroll
    for (int k = 0; k < ORDER; ++k)
        Vf[k] = *reinterpret_cast<const float4*>(v + k * NCOLS + c0);

    // ---- Gram ----
    {
        int idx = 0;
#pragma unroll
        for (int i = 0; i < ORDER; ++i) {
#pragma unroll
            for (int k = i; k < ORDER; ++k) {
                float gg = Vf[i].x * Vf[k].x;
                gg = fmaf(Vf[i].y, Vf[k].y, gg);
                gg = fmaf(Vf[i].z, Vf[k].z, gg);
                gg = fmaf(Vf[i].w, Vf[k].w, gg);
#pragma unroll
                for (int m = 16; m >= 1; m >>= 1)
                    gg += __shfl_xor_sync(0xffffffffu, gg, m);
                if (lane == 0) gpart[w * 36 + idx] = gg;
                ++idx;
            }
        }
    }
    __syncthreads();
    if (t < 36) {
        float s = 0.f;
#pragma unroll
        for (int ww = 0; ww < 16; ++ww) s += gpart[ww * 36 + t];
        gpart[t] = s;
    }
    __syncthreads();
    if (t == 0) {
        float Gs[ORDER][ORDER];
        int id2 = 0;
        for (int i = 0; i < ORDER; ++i)
            for (int k = i; k < ORDER; ++k) {
                Gs[i][k] = gpart[id2]; Gs[k][i] = gpart[id2]; ++id2;
            }
        float rn[ORDER];
        for (int i = 0; i < ORDER; ++i) rn[i] = 1.0f / sqrtf(Gs[i][i]);
        float T[ORDER][ORDER];
        for (int i = 0; i < ORDER; ++i)
            for (int k = 0; k < ORDER; ++k) T[i][k] = 0.f;
        for (int i = 0; i < ORDER; ++i) T[i][i] = 2.f;
        for (int c = 1; c < ORDER; ++c)
            for (int r = 0; r < c; ++r) {
                float s = 0.f;
                for (int m = r; m < c; ++m)
                    s += T[r][m] * (Gs[m][c] * rn[m] * rn[c]);
                T[r][c] = -2.f * s;
            }
        for (int i = 0; i < ORDER; ++i)
            for (int k = 0; k < ORDER; ++k)
                Tneg[i * 8 + k] = -(rn[i] * T[i][k] * rn[k]);
    }

    // ---- collapse chunk partials for this block's rows into A2 ----
    // [row][i][chunk(16)] contiguous -> 4 float4 loads per (row,i)
    if (t < 56 * 8) {
        const int row = t >> 3, i = t & 7;
        if (row < nr) {
            const float* base = &g_Apart[(size_t)(r0 + row) * 128 + i * 16];
            float a = 0.f;
#pragma unroll
            for (int c = 0; c < 4; ++c) {
                const float4 f4 = *reinterpret_cast<const float4*>(base + c * 4);
                a += (f4.x + f4.y) + (f4.z + f4.w);
            }
            A2[(row * 8 + i) * 2]     = a;
            A2[(row * 8 + i) * 2 + 1] = a;
        }
    }
    __syncthreads();

    // ---- W2 = Tneg * V (per-thread 4-col slice), then drop V ----
    ull W0[ORDER], W1[ORDER];
#pragma unroll
    for (int i = 0; i < ORDER; ++i) {
        float4 acc = make_float4(0.f, 0.f, 0.f, 0.f);
#pragma unroll
        for (int k = 0; k < ORDER; ++k) {
            const float tk = Tneg[i * 8 + k];
            acc.x = fmaf(tk, Vf[k].x, acc.x);
            acc.y = fmaf(tk, Vf[k].y, acc.y);
            acc.z = fmaf(tk, Vf[k].z, acc.z);
            acc.w = fmaf(tk, Vf[k].w, acc.w);
        }
        W0[i] = pack2(acc.x, acc.y);
        W1[i] = pack2(acc.z, acc.w);
    }

    const float4 dv = *reinterpret_cast<const float4*>(d + c0);
    const float4 bv = *reinterpret_cast<const float4*>(bias + c0);
    const ull d01 = pack2(dv.x, dv.y), d23 = pack2(dv.z, dv.w);
    const ull b01 = pack2(bv.x, bv.y), b23 = pack2(bv.z, bv.w);

    const float* xp = x + c0;
    float*       yp = y + c0;

    // ---- pure stream: every row fully independent ----
#pragma unroll 8
    for (int j = 0; j < nr; ++j) {
        const float4 xv = *reinterpret_cast<const float4*>(xp + (size_t)(r0 + j) * NCOLS);
        ull a01 = pack2(xv.x, xv.y);
        ull a23 = pack2(xv.z, xv.w);
#pragma unroll
        for (int i = 0; i < 8; ++i) {
            const ull aa = *reinterpret_cast<const ull*>(&A2[(j * 8 + i) * 2]);
            a01 = ffma2(aa, W0[i], a01);
            a23 = ffma2(aa, W1[i], a23);
        }
        a01 = ffma2(a01, d01, b01);
        a23 = ffma2(a23, d23, b23);
        const float2 o0 = unpack2(a01), o1 = unpack2(a23);
        __stcs(reinterpret_cast<float4*>(yp + (size_t)(r0 + j) * NCOLS),
               make_float4(o0.x, o0.y, o1.x, o1.y));
    }
}

extern "C" void kernel_launch(void* const* d_in, const int* in_sizes, int n_in,
                              void* d_out, int out_size) {
    const float* x    = (const float*)d_in[0];
    const float* v    = (const float*)d_in[1];
    const float* dvec = (const float*)d_in[2];
    const float* bias = (const float*)d_in[3];
    float* y = (float*)d_out;
    (void)in_sizes; (void)n_in; (void)out_size;

    k1_dots<<<NB, TPB>>>(x, v);
    k2_stream<<<NB, TPB>>>(x, v, dvec, bias, y);
}

// round 10
// speedup vs baseline: 1.2037x; 1.2037x over previous
#include <cuda_runtime.h>
#include <cstdint>

#define NCOLS 2048
#define ORDER 8
#define NB    148
#define TPB   512
#define TILE  8
#define NT    7

typedef unsigned long long ull;

__device__ __forceinline__ ull pack2(float lo, float hi) {
    ull r; asm("mov.b64 %0, {%1, %2};" : "=l"(r) : "f"(lo), "f"(hi)); return r;
}
__device__ __forceinline__ float2 unpack2(ull v) {
    float2 f; asm("mov.b64 {%0, %1}, %2;" : "=f"(f.x), "=f"(f.y) : "l"(v)); return f;
}
__device__ __forceinline__ ull ffma2(ull a, ull b, ull c) {
    ull d; asm("fma.rn.f32x2 %0, %1, %2, %3;" : "=l"(d) : "l"(a), "l"(b), "l"(c)); return d;
}
__device__ __forceinline__ ull fmul2(ull a, ull b) {
    ull d; asm("mul.rn.f32x2 %0, %1, %2;" : "=l"(d) : "l"(a), "l"(b)); return d;
}
__device__ __forceinline__ uint32_t s2u(const void* p) {
    uint32_t a;
    asm("{ .reg .u64 t; cvta.to.shared.u64 t, %1; cvt.u32.u64 %0, t; }"
        : "=r"(a) : "l"(p));
    return a;
}
__device__ __forceinline__ void cp16(uint32_t dst, const float* src) {
    asm volatile("cp.async.cg.shared.global [%0], [%1], 16;" :: "r"(dst), "l"(src));
}
__device__ __forceinline__ void cp_commit() {
    asm volatile("cp.async.commit_group;");
}
__device__ __forceinline__ void cp_wait0() {
    asm volatile("cp.async.wait_group 0;");
}

// dynamic smem: xbuf[2][TILE][NCOLS] = 131072 bytes
extern __shared__ float xbuf[];

__global__ void __launch_bounds__(TPB, 1) orth_pipe(
    const float* __restrict__ x, const float* __restrict__ v,
    const float* __restrict__ d, const float* __restrict__ bias,
    float* __restrict__ y)
{
    __shared__ float gpart[16 * 36];
    __shared__ float Tneg[64];
    __shared__ float asum[16 * 65];        // stride 65 -> conflict-free collapse
    __shared__ float A2[TILE * 8 * 2];     // duplicated (A,A) pairs

    const int t = threadIdx.x, lane = t & 31, w = t >> 5;
    const int c0 = t * 4;

    const int bid = blockIdx.x;
    const int nr = (bid < 52) ? 56 : 55;
    const int r0 = (bid < 52) ? bid * 56 : 52 * 56 + (bid - 52) * 55;

    // ---- kick off prefetch of tile 0 immediately ----
    const uint32_t xb_base = s2u(xbuf);
#pragma unroll
    for (int j = 0; j < TILE; ++j) {
        const int rc = (j < nr) ? j : (nr - 1);
        cp16(xb_base + (uint32_t)((0 * TILE + j) * NCOLS + c0) * 4,
             x + (size_t)(r0 + rc) * NCOLS + c0);
    }
    cp_commit();

    // ---- V slice ----
    float4 Vf[ORDER];
#pragma unroll
    for (int k = 0; k < ORDER; ++k)
        Vf[k] = *reinterpret_cast<const float4*>(v + k * NCOLS + c0);

    // ================= Prologue: Gram -> Tneg -> W2 =================
    {
        int idx = 0;
#pragma unroll
        for (int i = 0; i < ORDER; ++i) {
#pragma unroll
            for (int k = i; k < ORDER; ++k) {
                float gg = Vf[i].x * Vf[k].x;
                gg = fmaf(Vf[i].y, Vf[k].y, gg);
                gg = fmaf(Vf[i].z, Vf[k].z, gg);
                gg = fmaf(Vf[i].w, Vf[k].w, gg);
#pragma unroll
                for (int m = 16; m >= 1; m >>= 1)
                    gg += __shfl_xor_sync(0xffffffffu, gg, m);
                if (lane == 0) gpart[w * 36 + idx] = gg;
                ++idx;
            }
        }
    }
    __syncthreads();
    if (t < 36) {
        float s = 0.f;
#pragma unroll
        for (int ww = 0; ww < 16; ++ww) s += gpart[ww * 36 + t];
        gpart[t] = s;
    }
    __syncthreads();
    if (t == 0) {
        float Gs[ORDER][ORDER];
        int id2 = 0;
        for (int i = 0; i < ORDER; ++i)
            for (int k = i; k < ORDER; ++k) {
                Gs[i][k] = gpart[id2]; Gs[k][i] = gpart[id2]; ++id2;
            }
        float rn[ORDER];
        for (int i = 0; i < ORDER; ++i) rn[i] = 1.0f / sqrtf(Gs[i][i]);
        float T[ORDER][ORDER];
        for (int i = 0; i < ORDER; ++i)
            for (int k = 0; k < ORDER; ++k) T[i][k] = 0.f;
        for (int i = 0; i < ORDER; ++i) T[i][i] = 2.f;
        for (int c = 1; c < ORDER; ++c)
            for (int r = 0; r < c; ++r) {
                float s = 0.f;
                for (int m = r; m < c; ++m)
                    s += T[r][m] * (Gs[m][c] * rn[m] * rn[c]);
                T[r][c] = -2.f * s;
            }
        for (int i = 0; i < ORDER; ++i)
            for (int k = 0; k < ORDER; ++k)
                Tneg[i * 8 + k] = -(rn[i] * T[i][k] * rn[k]);
    }
    __syncthreads();

    // W2 = Tneg * V; keep BOTH V (dots) and W2 (correction), packed.
    ull V0[ORDER], V1[ORDER], W0[ORDER], W1[ORDER];
#pragma unroll
    for (int i = 0; i < ORDER; ++i) {
        float4 acc = make_float4(0.f, 0.f, 0.f, 0.f);
#pragma unroll
        for (int k = 0; k < ORDER; ++k) {
            const float tk = Tneg[i * 8 + k];
            acc.x = fmaf(tk, Vf[k].x, acc.x);
            acc.y = fmaf(tk, Vf[k].y, acc.y);
            acc.z = fmaf(tk, Vf[k].z, acc.z);
            acc.w = fmaf(tk, Vf[k].w, acc.w);
        }
        W0[i] = pack2(acc.x, acc.y);
        W1[i] = pack2(acc.z, acc.w);
        V0[i] = pack2(Vf[i].x, Vf[i].y);
        V1[i] = pack2(Vf[i].z, Vf[i].w);
    }

    const float4 dv = *reinterpret_cast<const float4*>(d + c0);
    const float4 bv = *reinterpret_cast<const float4*>(bias + c0);
    const ull d01 = pack2(dv.x, dv.y), d23 = pack2(dv.z, dv.w);
    const ull b01 = pack2(bv.x, bv.y), b23 = pack2(bv.z, bv.w);

    float* yp = y + c0;

    // ================= Pipelined main loop =================
#pragma unroll 1
    for (int tt = 0; tt < NT; ++tt) {
        const int buf = tt & 1;

        cp_wait0();
        __syncthreads();               // tile tt visible; prev pass C done

        // prefetch tile tt+1 into the other buffer
        if (tt + 1 < NT) {
#pragma unroll
            for (int j = 0; j < TILE; ++j) {
                const int jr = (tt + 1) * TILE + j;
                const int rc = (jr < nr) ? jr : (nr - 1);
                cp16(xb_base + (uint32_t)(((1 - buf) * TILE + j) * NCOLS + c0) * 4,
                     x + (size_t)(r0 + rc) * NCOLS + c0);
            }
            cp_commit();
        }

        const float* xs = &xbuf[buf * TILE * NCOLS];

        // ---- pass A: dots from smem + butterfly -> asum ----
#pragma unroll
        for (int j = 0; j < TILE; ++j) {
            const float4 xv = *reinterpret_cast<const float4*>(xs + j * NCOLS + c0);
            const ull x01 = pack2(xv.x, xv.y);
            const ull x23 = pack2(xv.z, xv.w);
            float p[8];
#pragma unroll
            for (int k = 0; k < 8; ++k) {
                const float2 f = unpack2(ffma2(x23, V1[k], fmul2(x01, V0[k])));
                p[k] = f.x + f.y;
            }
#pragma unroll
            for (int k = 0; k < 8; ++k) {
                p[k] += __shfl_xor_sync(0xffffffffu, p[k], 16);
                p[k] += __shfl_xor_sync(0xffffffffu, p[k], 8);
            }
            const bool h4 = (lane & 4) != 0;
            float q[4];
#pragma unroll
            for (int jj = 0; jj < 4; ++jj) {
                float keep = h4 ? p[jj + 4] : p[jj];
                float send = h4 ? p[jj] : p[jj + 4];
                q[jj] = keep + __shfl_xor_sync(0xffffffffu, send, 4);
            }
            const bool h2 = (lane & 2) != 0;
            float r2[2];
#pragma unroll
            for (int jj = 0; jj < 2; ++jj) {
                float keep = h2 ? q[jj + 2] : q[jj];
                float send = h2 ? q[jj] : q[jj + 2];
                r2[jj] = keep + __shfl_xor_sync(0xffffffffu, send, 2);
            }
            const bool h1 = (lane & 1) != 0;
            float keep = h1 ? r2[1] : r2[0];
            float send = h1 ? r2[0] : r2[1];
            const float s = keep + __shfl_xor_sync(0xffffffffu, send, 1);
            if (lane < 8) asum[w * 65 + j * 8 + lane] = s;
        }
        __syncthreads();

        // ---- pass B: collapse 16 warps (64 threads; stride-65 conflict-free)
        if (t < TILE * 8) {
            float a = 0.f;
#pragma unroll
            for (int ww = 0; ww < 16; ++ww) a += asum[ww * 65 + t];
            A2[t * 2] = a;
            A2[t * 2 + 1] = a;
        }
        __syncthreads();

        // ---- pass C: correction + scale + store (x from smem) ----
#pragma unroll
        for (int j = 0; j < TILE; ++j) {
            const int jr = tt * TILE + j;
            if (jr < nr) {
                const float4 xv = *reinterpret_cast<const float4*>(xs + j * NCOLS + c0);
                ull a01 = pack2(xv.x, xv.y);
                ull a23 = pack2(xv.z, xv.w);
#pragma unroll
                for (int i = 0; i < 8; ++i) {
                    const ull aa = *reinterpret_cast<const ull*>(&A2[(j * 8 + i) * 2]);
                    a01 = ffma2(aa, W0[i], a01);
                    a23 = ffma2(aa, W1[i], a23);
                }
                a01 = ffma2(a01, d01, b01);
                a23 = ffma2(a23, d23, b23);
                const float2 o0 = unpack2(a01), o1 = unpack2(a23);
                __stcs(reinterpret_cast<float4*>(yp + (size_t)(r0 + jr) * NCOLS),
                       make_float4(o0.x, o0.y, o1.x, o1.y));
            }
        }
    }
}

extern "C" void kernel_launch(void* const* d_in, const int* in_sizes, int n_in,
                              void* d_out, int out_size) {
    const float* x    = (const float*)d_in[0];
    const float* v    = (const float*)d_in[1];
    const float* dvec = (const float*)d_in[2];
    const float* bias = (const float*)d_in[3];
    float* y = (float*)d_out;
    (void)in_sizes; (void)n_in; (void)out_size;

    const int dyn = 2 * TILE * NCOLS * (int)sizeof(float);   // 131072 B
    static int attr_set = 0;
    if (!attr_set) {
        cudaFuncSetAttribute(orth_pipe,
                             cudaFuncAttributeMaxDynamicSharedMemorySize, dyn);
        attr_set = 1;
    }
    orth_pipe<<<NB, TPB, dyn>>>(x, v, dvec, bias, y);
}